// round 7
// baseline (speedup 1.0000x reference)
#include <cuda_runtime.h>
#include <cuda_bf16.h>

#define NLAGS   250
#define LPAD    256          // padded lag count (lags >= 250 computed on zero-padded halo, discarded)
#define TILE_J  1024
#define NBLOCKS 592          // 4 CTAs/SM * 148 SMs
#define THREADS 256
#define GPAD_SZ 1440         // phys size for logical 1280 floats with i + (i>>3) padding

// Deterministic reduction scratch (no allocs allowed)
__device__ float  g_partialT[LPAD * NBLOCKS];   // transposed: lag-major, contiguous per lag
__device__ float4 g_sums4[NBLOCKS];
__device__ float  g_cross[LPAD];
__device__ float4 g_tot;

// ---------------------------------------------------------------------------
// Kernel A: per-block partial cross-correlations for 256 lags + partial sums.
// Each warp handles 128 j's per tile; each lane handles 8 consecutive lags
// with a register sliding window over g (conflict-free via padded smem).
// Partials written TRANSPOSED so kernel B1 reads each lag contiguously.
// ---------------------------------------------------------------------------
__global__ void __launch_bounds__(THREADS) cccorr_kernel(const float* __restrict__ p,
                                                         const float* __restrict__ g,
                                                         int T) {
    __shared__ float p_s[TILE_J];
    __shared__ float g_s[GPAD_SZ];
    __shared__ float red[8 * LPAD];

    const int tid    = threadIdx.x;
    const int lane   = tid & 31;
    const int warpId = tid >> 5;
    const int jj0    = warpId * 128;   // warp's j sub-slice within tile
    const int n0     = lane * 8;       // lane's base lag

    float acc[8];
#pragma unroll
    for (int k = 0; k < 8; k++) acc[k] = 0.f;
    float sp = 0.f, sp2 = 0.f, sg = 0.f, sg2 = 0.f;

    const int ntiles = (T + TILE_J - 1) / TILE_J;
    for (int tile = blockIdx.x; tile < ntiles; tile += NBLOCKS) {
        const int base = tile * TILE_J;

        // Load p tile (zero-padded) + accumulate sums
        for (int i = tid; i < TILE_J; i += THREADS) {
            int gi = base + i;
            float v = (gi < T) ? p[gi] : 0.f;
            p_s[i] = v;
            sp += v; sp2 += v * v;
        }
        // Load g tile + 256 halo into padded smem (zero-padded past T)
        for (int i = tid; i < TILE_J + LPAD; i += THREADS) {
            int gi = base + i;
            float v = (gi < T) ? g[gi] : 0.f;
            g_s[i + (i >> 3)] = v;
            if (i < TILE_J) { sg += v; sg2 += v * v; }
        }
        __syncthreads();

        // Sliding-window cross-correlation: acc[k] += sum_j p[j] * g[j + n0 + k]
        float w[8];
#pragma unroll
        for (int k = 0; k < 8; k++) {
            int li = jj0 + n0 + k;
            w[k] = g_s[li + (li >> 3)];
        }
#pragma unroll 8
        for (int jj = 0; jj < 128; jj++) {
            float pv = p_s[jj0 + jj];
#pragma unroll
            for (int k = 0; k < 8; k++) acc[k] = fmaf(pv, w[k], acc[k]);
            int li = jj0 + jj + n0 + 8;        // next window top (lane-stride 9 in phys -> no conflict)
            float nv = g_s[li + (li >> 3)];
#pragma unroll
            for (int k = 0; k < 7; k++) w[k] = w[k + 1];
            w[7] = nv;
        }
        __syncthreads();
    }

    // Reduce 8 warps' partials per lag -> one partial row per block (transposed write)
#pragma unroll
    for (int k = 0; k < 8; k++) red[warpId * LPAD + n0 + k] = acc[k];
    __syncthreads();
    {
        float s = 0.f;
#pragma unroll
        for (int w = 0; w < 8; w++) s += red[w * LPAD + tid];
        g_partialT[tid * NBLOCKS + blockIdx.x] = s;
    }

    // Reduce the 4 scalar sums
#pragma unroll
    for (int off = 16; off; off >>= 1) {
        sp  += __shfl_down_sync(0xFFFFFFFFu, sp,  off);
        sp2 += __shfl_down_sync(0xFFFFFFFFu, sp2, off);
        sg  += __shfl_down_sync(0xFFFFFFFFu, sg,  off);
        sg2 += __shfl_down_sync(0xFFFFFFFFu, sg2, off);
    }
    __shared__ float sred[8][4];
    if (lane == 0) {
        sred[warpId][0] = sp;  sred[warpId][1] = sp2;
        sred[warpId][2] = sg;  sred[warpId][3] = sg2;
    }
    __syncthreads();
    if (tid < 4) {
        float t = 0.f;
#pragma unroll
        for (int w = 0; w < 8; w++) t += sred[w][tid];
        ((float*)&g_sums4[blockIdx.x])[tid] = t;
    }
}

// ---------------------------------------------------------------------------
// Kernel B1: grid-parallel reduction. Blocks 0..249 reduce one lag each
// (592 contiguous floats, coalesced). Block 250 reduces the float4 sums.
// ---------------------------------------------------------------------------
#define B1_THREADS 128

__global__ void __launch_bounds__(B1_THREADS) reduce_kernel() {
    const int t    = threadIdx.x;
    const int lane = t & 31;
    const int wp   = t >> 5;
    const int lag  = blockIdx.x;

    if (lag < NLAGS) {
        const float* base = g_partialT + lag * NBLOCKS;
        float s = 0.f;
#pragma unroll
        for (int i = 0; i < 4; i++) s += base[t + i * B1_THREADS];   // 512 rows
        if (t < NBLOCKS - 4 * B1_THREADS) s += base[4 * B1_THREADS + t];  // +80
#pragma unroll
        for (int off = 16; off; off >>= 1) s += __shfl_down_sync(0xFFFFFFFFu, s, off);
        __shared__ float ws[4];
        if (lane == 0) ws[wp] = s;
        __syncthreads();
        if (t == 0) g_cross[lag] = (ws[0] + ws[1]) + (ws[2] + ws[3]);
    } else {
        // block 250: reduce g_sums4
        float x = 0.f, y = 0.f, z = 0.f, w = 0.f;
        for (int i = t; i < NBLOCKS; i += B1_THREADS) {
            float4 v = g_sums4[i];
            x += v.x; y += v.y; z += v.z; w += v.w;
        }
#pragma unroll
        for (int off = 16; off; off >>= 1) {
            x += __shfl_down_sync(0xFFFFFFFFu, x, off);
            y += __shfl_down_sync(0xFFFFFFFFu, y, off);
            z += __shfl_down_sync(0xFFFFFFFFu, z, off);
            w += __shfl_down_sync(0xFFFFFFFFu, w, off);
        }
        __shared__ float4 ws4[4];
        if (lane == 0) ws4[wp] = make_float4(x, y, z, w);
        __syncthreads();
        if (t == 0) {
            float4 a = ws4[0], b = ws4[1], c = ws4[2], d = ws4[3];
            g_tot = make_float4((a.x + b.x) + (c.x + d.x),
                                (a.y + b.y) + (c.y + d.y),
                                (a.z + b.z) + (c.z + d.z),
                                (a.w + b.w) + (c.w + d.w));
        }
    }
}

// ---------------------------------------------------------------------------
// Kernel B2: tiny finalize. Tail scan + per-lag CCC + scalar output.
// ---------------------------------------------------------------------------
__global__ void __launch_bounds__(LPAD) finalize_kernel(const float* __restrict__ p,
                                                        int T,
                                                        float* __restrict__ out) {
    __shared__ float scanA[LPAD], scanB[LPAD];
    __shared__ float scan2A[LPAD], scan2B[LPAD];
    __shared__ float cccs[LPAD];

    const int tid = threadIdx.x;

    // Tail values + Hillis-Steele inclusive scan (8 steps)
    {
        float v = (tid >= 1) ? p[T - tid] : 0.f;
        scanA[tid]  = v;
        scan2A[tid] = v * v;
    }
    __syncthreads();
#pragma unroll
    for (int s = 0; s < 8; s++) {
        int off = 1 << s;
        float a  = scanA[tid]  + ((tid >= off) ? scanA[tid - off]  : 0.f);
        float a2 = scan2A[tid] + ((tid >= off) ? scan2A[tid - off] : 0.f);
        __syncthreads();
        scanB[tid] = a; scan2B[tid] = a2;
        __syncthreads();
        scanA[tid] = scanB[tid]; scan2A[tid] = scan2B[tid];
        __syncthreads();
    }

    const float4 tot = g_tot;
    const float Sp  = tot.x, Sp2 = tot.y;
    const float Sg  = tot.z, Sg2 = tot.w;
    const float Tf  = (float)T;
    const float mean_gt = Sg / Tf;
    const float var_gt  = (Sg2 - Tf * mean_gt * mean_gt) / (Tf - 1.f);

    float ccc = 0.f;
    if (tid < NLAGS) {
        float cross = g_cross[tid];
        float Spn   = Sp  - scanA[tid];     // sum of p[0 : T-n]
        float Spn2  = Sp2 - scan2A[tid];
        float mean_pred = Spn / Tf;
        float var_pred  = (Spn2 - Tf * mean_pred * mean_pred) / (Tf - 1.f);
        float cov = (cross - mean_gt * Spn) / Tf;   // population covariance
        float dm  = mean_gt - mean_pred;
        float denom = var_gt + var_pred + dm * dm;
        ccc = 2.f * cov / denom;
    }
    cccs[tid] = ccc;
    __syncthreads();
#pragma unroll
    for (int off = LPAD / 2; off >= 1; off >>= 1) {
        if (tid < off) cccs[tid] += cccs[tid + off];
        __syncthreads();
    }
    if (tid == 0) out[0] = 1.f - cccs[0] / (float)NLAGS;
}

extern "C" void kernel_launch(void* const* d_in, const int* in_sizes, int n_in,
                              void* d_out, int out_size) {
    const float* pred = (const float*)d_in[0];
    const float* gt   = (const float*)d_in[1];
    float* out = (float*)d_out;
    int T = in_sizes[0];

    cccorr_kernel<<<NBLOCKS, THREADS>>>(pred, gt, T);
    reduce_kernel<<<NLAGS + 1, B1_THREADS>>>();
    finalize_kernel<<<1, LPAD>>>(pred, T, out);
}

// round 8
// speedup vs baseline: 1.6047x; 1.6047x over previous
#include <cuda_runtime.h>
#include <cuda_bf16.h>

#define NLAGS   250
#define LPAD    256
#define TILE_J  1024
#define NBLOCKS 592          // 4 CTAs/SM * 148 SMs
#define THREADS 256
#define GLOG    1304         // logical g floats per tile (TILE_J + 256 + slack)
#define GPAD_F4 490          // float4 count of padded phys array (phys = i + 4*(i>>3))

// Deterministic reduction scratch (no allocs allowed)
__device__ float  g_partialT[LPAD * NBLOCKS];   // transposed: lag-major, contiguous per lag
__device__ float4 g_sums4[NBLOCKS];
__device__ float  g_cross[LPAD];
__device__ float4 g_tot;

// 8 j's x 8 lags outer product against a 15-element window (Q0..Q3 = 16 floats, s[15] used)
static __device__ __forceinline__ void batch8(float4 Q0, float4 Q1, float4 Q2, float4 Q3,
                                              float4 P0, float4 P1, float* acc) {
    const float sv[16] = {Q0.x, Q0.y, Q0.z, Q0.w, Q1.x, Q1.y, Q1.z, Q1.w,
                          Q2.x, Q2.y, Q2.z, Q2.w, Q3.x, Q3.y, Q3.z, Q3.w};
    const float pv[8]  = {P0.x, P0.y, P0.z, P0.w, P1.x, P1.y, P1.z, P1.w};
#pragma unroll
    for (int i = 0; i < 8; i++)
#pragma unroll
        for (int k = 0; k < 8; k++)
            acc[k] = fmaf(pv[i], sv[i + k], acc[k]);
}

// ---------------------------------------------------------------------------
// Kernel A: per-block partial cross-correlations for 256 lags + partial sums.
// Each warp handles 128 j's per tile (16 batches of 8); each lane owns 8
// consecutive lags. g stored with 4-per-8 padding: phys = i + 4*(i>>3) ->
// lane stride 48B, conflict-free + 16B-aligned LDS.128 refills.
// ---------------------------------------------------------------------------
__global__ void __launch_bounds__(THREADS, 4) cccorr_kernel(const float* __restrict__ p,
                                                            const float* __restrict__ g,
                                                            int T) {
    __shared__ __align__(16) float p_s[TILE_J];
    __shared__ __align__(16) float g_s[GPAD_F4 * 4];
    __shared__ float red[8 * LPAD];

    const int tid    = threadIdx.x;
    const int lane   = tid & 31;
    const int warpId = tid >> 5;
    const int jj0    = warpId * 128;   // warp's j sub-slice within tile
    const int n0     = lane * 8;       // lane's base lag

    float acc[8];
#pragma unroll
    for (int k = 0; k < 8; k++) acc[k] = 0.f;
    float sp = 0.f, sp2 = 0.f, sg = 0.f, sg2 = 0.f;

    const float4* gq = (const float4*)g_s;
    const float4* pq = (const float4*)p_s;
    // logical window start for this (warp, lane): li0 = jj0 + n0, mult of 8
    // f4 base index: phys(li0)/4 = 3*(li0>>3)
    const int f0  = 3 * ((jj0 + n0) >> 3);
    const int pq0 = jj0 >> 2;

    const int ntiles = (T + TILE_J - 1) / TILE_J;
    for (int tile = blockIdx.x; tile < ntiles; tile += NBLOCKS) {
        const int base = tile * TILE_J;

        // Load p tile (zero-padded) + accumulate sums
        for (int i = tid; i < TILE_J; i += THREADS) {
            int gi = base + i;
            float v = (gi < T) ? p[gi] : 0.f;
            p_s[i] = v;
            sp += v; sp2 += v * v;
        }
        // Load g tile + halo, padded phys = i + 4*(i>>3), zero past T
        for (int i = tid; i < GLOG; i += THREADS) {
            int gi = base + i;
            float v = (gi < T) ? g[gi] : 0.f;
            g_s[i + ((i >> 3) << 2)] = v;
            if (i < TILE_J) { sg += v; sg2 += v * v; }
        }
        __syncthreads();

        // 16 batches of 8 j's; window quads A0..A3 cover 16 logical floats at
        // f4 indices {0,1,3,4} relative to the sliding base (index 2 = pad).
        float4 A0 = gq[f0 + 0], A1 = gq[f0 + 1], A2 = gq[f0 + 3], A3 = gq[f0 + 4];
#pragma unroll 2
        for (int t = 0; t < 16; t += 2) {
            const int fq = f0 + 3 * t;
            float4 P0 = pq[pq0 + 2 * t], P1 = pq[pq0 + 2 * t + 1];
            batch8(A0, A1, A2, A3, P0, P1, acc);
            A0 = gq[fq + 6]; A1 = gq[fq + 7];
            P0 = pq[pq0 + 2 * t + 2]; P1 = pq[pq0 + 2 * t + 3];
            batch8(A2, A3, A0, A1, P0, P1, acc);
            A2 = gq[fq + 9]; A3 = gq[fq + 10];
        }
        __syncthreads();
    }

    // Reduce 8 warps' partials per lag -> one partial row per block (transposed write)
#pragma unroll
    for (int k = 0; k < 8; k++) red[warpId * LPAD + n0 + k] = acc[k];
    __syncthreads();
    {
        float s = 0.f;
#pragma unroll
        for (int w = 0; w < 8; w++) s += red[w * LPAD + tid];
        g_partialT[tid * NBLOCKS + blockIdx.x] = s;
    }

    // Reduce the 4 scalar sums
#pragma unroll
    for (int off = 16; off; off >>= 1) {
        sp  += __shfl_down_sync(0xFFFFFFFFu, sp,  off);
        sp2 += __shfl_down_sync(0xFFFFFFFFu, sp2, off);
        sg  += __shfl_down_sync(0xFFFFFFFFu, sg,  off);
        sg2 += __shfl_down_sync(0xFFFFFFFFu, sg2, off);
    }
    __shared__ float sred[8][4];
    if (lane == 0) {
        sred[warpId][0] = sp;  sred[warpId][1] = sp2;
        sred[warpId][2] = sg;  sred[warpId][3] = sg2;
    }
    __syncthreads();
    if (tid < 4) {
        float t = 0.f;
#pragma unroll
        for (int w = 0; w < 8; w++) t += sred[w][tid];
        ((float*)&g_sums4[blockIdx.x])[tid] = t;
    }
}

// ---------------------------------------------------------------------------
// Kernel B1: grid-parallel reduction. Blocks 0..249 reduce one lag each
// (592 contiguous floats, coalesced). Block 250 reduces the float4 sums.
// ---------------------------------------------------------------------------
#define B1_THREADS 128

__global__ void __launch_bounds__(B1_THREADS) reduce_kernel() {
    const int t    = threadIdx.x;
    const int lane = t & 31;
    const int wp   = t >> 5;
    const int lag  = blockIdx.x;

    if (lag < NLAGS) {
        const float* base = g_partialT + lag * NBLOCKS;
        float s = 0.f;
#pragma unroll
        for (int i = 0; i < 4; i++) s += base[t + i * B1_THREADS];   // 512 rows
        if (t < NBLOCKS - 4 * B1_THREADS) s += base[4 * B1_THREADS + t];  // +80
#pragma unroll
        for (int off = 16; off; off >>= 1) s += __shfl_down_sync(0xFFFFFFFFu, s, off);
        __shared__ float ws[4];
        if (lane == 0) ws[wp] = s;
        __syncthreads();
        if (t == 0) g_cross[lag] = (ws[0] + ws[1]) + (ws[2] + ws[3]);
    } else {
        // block 250: reduce g_sums4
        float x = 0.f, y = 0.f, z = 0.f, w = 0.f;
        for (int i = t; i < NBLOCKS; i += B1_THREADS) {
            float4 v = g_sums4[i];
            x += v.x; y += v.y; z += v.z; w += v.w;
        }
#pragma unroll
        for (int off = 16; off; off >>= 1) {
            x += __shfl_down_sync(0xFFFFFFFFu, x, off);
            y += __shfl_down_sync(0xFFFFFFFFu, y, off);
            z += __shfl_down_sync(0xFFFFFFFFu, z, off);
            w += __shfl_down_sync(0xFFFFFFFFu, w, off);
        }
        __shared__ float4 ws4[4];
        if (lane == 0) ws4[wp] = make_float4(x, y, z, w);
        __syncthreads();
        if (t == 0) {
            float4 a = ws4[0], b = ws4[1], c = ws4[2], d = ws4[3];
            g_tot = make_float4((a.x + b.x) + (c.x + d.x),
                                (a.y + b.y) + (c.y + d.y),
                                (a.z + b.z) + (c.z + d.z),
                                (a.w + b.w) + (c.w + d.w));
        }
    }
}

// ---------------------------------------------------------------------------
// Kernel B2: tiny finalize. Tail scan + per-lag CCC + scalar output.
// ---------------------------------------------------------------------------
__global__ void __launch_bounds__(LPAD) finalize_kernel(const float* __restrict__ p,
                                                        int T,
                                                        float* __restrict__ out) {
    __shared__ float scanA[LPAD], scanB[LPAD];
    __shared__ float scan2A[LPAD], scan2B[LPAD];
    __shared__ float cccs[LPAD];

    const int tid = threadIdx.x;

    // Tail values + Hillis-Steele inclusive scan (8 steps)
    {
        float v = (tid >= 1) ? p[T - tid] : 0.f;
        scanA[tid]  = v;
        scan2A[tid] = v * v;
    }
    __syncthreads();
#pragma unroll
    for (int s = 0; s < 8; s++) {
        int off = 1 << s;
        float a  = scanA[tid]  + ((tid >= off) ? scanA[tid - off]  : 0.f);
        float a2 = scan2A[tid] + ((tid >= off) ? scan2A[tid - off] : 0.f);
        __syncthreads();
        scanB[tid] = a; scan2B[tid] = a2;
        __syncthreads();
        scanA[tid] = scanB[tid]; scan2A[tid] = scan2B[tid];
        __syncthreads();
    }

    const float4 tot = g_tot;
    const float Sp  = tot.x, Sp2 = tot.y;
    const float Sg  = tot.z, Sg2 = tot.w;
    const float Tf  = (float)T;
    const float mean_gt = Sg / Tf;
    const float var_gt  = (Sg2 - Tf * mean_gt * mean_gt) / (Tf - 1.f);

    float ccc = 0.f;
    if (tid < NLAGS) {
        float cross = g_cross[tid];
        float Spn   = Sp  - scanA[tid];     // sum of p[0 : T-n]
        float Spn2  = Sp2 - scan2A[tid];
        float mean_pred = Spn / Tf;
        float var_pred  = (Spn2 - Tf * mean_pred * mean_pred) / (Tf - 1.f);
        float cov = (cross - mean_gt * Spn) / Tf;   // population covariance
        float dm  = mean_gt - mean_pred;
        float denom = var_gt + var_pred + dm * dm;
        ccc = 2.f * cov / denom;
    }
    cccs[tid] = ccc;
    __syncthreads();
#pragma unroll
    for (int off = LPAD / 2; off >= 1; off >>= 1) {
        if (tid < off) cccs[tid] += cccs[tid + off];
        __syncthreads();
    }
    if (tid == 0) out[0] = 1.f - cccs[0] / (float)NLAGS;
}

extern "C" void kernel_launch(void* const* d_in, const int* in_sizes, int n_in,
                              void* d_out, int out_size) {
    const float* pred = (const float*)d_in[0];
    const float* gt   = (const float*)d_in[1];
    float* out = (float*)d_out;
    int T = in_sizes[0];

    cccorr_kernel<<<NBLOCKS, THREADS>>>(pred, gt, T);
    reduce_kernel<<<NLAGS + 1, B1_THREADS>>>();
    finalize_kernel<<<1, LPAD>>>(pred, T, out);
}